// round 14
// baseline (speedup 1.0000x reference)
#include <cuda_runtime.h>
#include <cuda_fp16.h>
#include <math.h>
#include <stdint.h>

#define N_NODES 50000
#define N_EDGES 800000
#define F_DIM   64
#define AVG_D_LOG 2.833f
#define EPS_STD 1e-5f
#define EPS_BN  1e-5f
#define NB 196   // ceil(50000/256)
#define A_FLAG 0x40000000u
#define P_FLAG 0x80000000u

typedef unsigned long long ull;

// ---------------- device scratch (all zero-initialized at load) ----------------
__device__ int   g_deg[N_NODES];       // zeroed by k_agg after use
__device__ int   g_off[N_NODES];
__device__ int   g_cursor[N_NODES];
__device__ int   g_esrc[N_EDGES];
__device__ unsigned g_pkt[NB];         // scan lookback state; zeroed by k_agg
__device__ unsigned g_a16[(size_t)N_NODES * 128];  // agg rows as fp16x2 words
__device__ float g_c1[N_NODES];
__device__ float g_c2[N_NODES];
__device__ float g_x[(size_t)N_NODES * F_DIM];
__device__ float g_colsum[F_DIM];
__device__ float g_colsq[F_DIM];
__device__ __half g_whi[64 * 768];     // W^T fp16 [n][k]

// ---------------- helpers -------------------------------------------------------
__device__ __forceinline__ uint32_t smem_u32(const void* p) {
    uint32_t r;
    asm("{ .reg .u64 t; cvta.to.shared.u64 t, %1; cvt.u32.u64 %0, t; }"
        : "=r"(r) : "l"(p));
    return r;
}
__device__ __forceinline__ void ldsm4(uint32_t& r0, uint32_t& r1,
                                      uint32_t& r2, uint32_t& r3, uint32_t a) {
    asm volatile("ldmatrix.sync.aligned.m8n8.x4.shared.b16 {%0,%1,%2,%3}, [%4];"
                 : "=r"(r0), "=r"(r1), "=r"(r2), "=r"(r3) : "r"(a));
}
__device__ __forceinline__ void mma_f16(float* d,
                                        uint32_t a0, uint32_t a1, uint32_t a2, uint32_t a3,
                                        uint32_t b0, uint32_t b1) {
    asm volatile(
        "mma.sync.aligned.m16n8k16.row.col.f32.f16.f16.f32 "
        "{%0,%1,%2,%3}, {%4,%5,%6,%7}, {%8,%9}, {%0,%1,%2,%3};"
        : "+f"(d[0]), "+f"(d[1]), "+f"(d[2]), "+f"(d[3])
        : "r"(a0), "r"(a1), "r"(a2), "r"(a3), "r"(b0), "r"(b1));
}
__device__ __forceinline__ uint32_t packh(float x, float y) {
    __half2 t;
    t.x = __float2half_rn(x);
    t.y = __float2half_rn(y);
    return *(uint32_t*)&t;
}
// cp.async 16B with zero-fill (src_bytes = 0 -> zfill, no read)
__device__ __forceinline__ void cp16z(uint32_t s, const void* g, unsigned srcbytes) {
    asm volatile(
        "{ .reg .u64 ga; cvta.to.global.u64 ga, %1;\n\t"
        "cp.async.cg.shared.global [%0], [ga], 16, %2; }"
        :: "r"(s), "l"(g), "r"(srcbytes) : "memory");
}
#define CP_COMMIT() asm volatile("cp.async.commit_group;" ::: "memory")
#define CP_WAIT(n)  asm volatile("cp.async.wait_group %0;" :: "n"(n) : "memory")
// packed f32x2 (add/fma only on this toolchain)
__device__ __forceinline__ void add2(ull& d, ull a) {
    asm("add.rn.f32x2 %0, %0, %1;" : "+l"(d) : "l"(a));
}
__device__ __forceinline__ void fma2(ull& d, ull a) {
    asm("fma.rn.f32x2 %0, %1, %1, %0;" : "+l"(d) : "l"(a));
}
__device__ __forceinline__ float lo32(ull v) { return __uint_as_float((unsigned)v); }
__device__ __forceinline__ float hi32(ull v) { return __uint_as_float((unsigned)(v >> 32)); }

// ---------------- K1: degree histogram (int4) + W fp16 transpose ------------------
__global__ void k_hist_wprep(const int* __restrict__ dst, const float* __restrict__ W) {
    int t = blockIdx.x * blockDim.x + threadIdx.x;
    if (t < N_EDGES / 4) {
        int4 d4 = ((const int4*)dst)[t];
        atomicAdd(&g_deg[d4.x], 1);
        atomicAdd(&g_deg[d4.y], 1);
        atomicAdd(&g_deg[d4.z], 1);
        atomicAdd(&g_deg[d4.w], 1);
    }
    if (t < 768 * 64) {
        int k = t >> 6;
        int n = t & 63;
        g_whi[n * 768 + k] = __float2half_rn(W[t]);
    }
}

// ---------------- K2: single-pass decoupled-lookback scan -------------------------
__global__ void k_scan(void) {
    __shared__ int s[256];
    __shared__ unsigned sprefix;
    int t = threadIdx.x;
    int bidx = blockIdx.x;
    int i = bidx * 256 + t;
    int v = (i < N_NODES) ? g_deg[i] : 0;
    s[t] = v;
    __syncthreads();
    #pragma unroll
    for (int off = 1; off < 256; off <<= 1) {
        int x = (t >= off) ? s[t - off] : 0;
        __syncthreads();
        s[t] += x;
        __syncthreads();
    }
    int total = s[255];

    if (t == 0) {
        unsigned pub = (bidx == 0) ? (P_FLAG | (unsigned)total)
                                   : (A_FLAG | (unsigned)total);
        atomicExch(&g_pkt[bidx], pub);
        if (bidx == 0) sprefix = 0;
    }

    if (bidx > 0 && t < 32) {
        unsigned running = 0;
        int idx = bidx - 1;
        for (;;) {
            int j = idx - t;
            unsigned p;
            if (j >= 0) {
                do { p = ((volatile unsigned*)g_pkt)[j]; } while (p == 0);
            } else {
                p = P_FLAG;
            }
            unsigned pm = __ballot_sync(0xffffffffu, (p & P_FLAG) != 0);
            unsigned val = p & 0x3fffffffu;
            if (pm) {
                int k = __ffs(pm) - 1;
                unsigned contrib = (t <= k) ? val : 0;
                #pragma unroll
                for (int o = 16; o > 0; o >>= 1)
                    contrib += __shfl_down_sync(0xffffffffu, contrib, o);
                if (t == 0) sprefix = running + contrib;
                break;
            } else {
                unsigned contrib = (j >= 0) ? val : 0;
                #pragma unroll
                for (int o = 16; o > 0; o >>= 1)
                    contrib += __shfl_down_sync(0xffffffffu, contrib, o);
                running += __shfl_sync(0xffffffffu, contrib, 0);
                idx -= 32;
            }
        }
        if (t == 0)
            atomicExch(&g_pkt[bidx], P_FLAG | (sprefix + (unsigned)total));
    }
    __syncthreads();

    if (i < N_NODES) {
        int ex = (int)sprefix + s[t] - v;
        g_off[i] = ex;
        g_cursor[i] = ex;
    }
}

// ---------------- K3: scatter edges, 4 per thread (MLP=4) -------------------------
__global__ void k_scatter(const int* __restrict__ src, const int* __restrict__ dst) {
    int t = blockIdx.x * blockDim.x + threadIdx.x;
    if (t >= N_EDGES / 4) return;
    int4 d4 = ((const int4*)dst)[t];
    int4 s4 = ((const int4*)src)[t];
    int p0 = atomicAdd(&g_cursor[d4.x], 1);
    int p1 = atomicAdd(&g_cursor[d4.y], 1);
    int p2 = atomicAdd(&g_cursor[d4.z], 1);
    int p3 = atomicAdd(&g_cursor[d4.w], 1);
    g_esrc[p0] = s4.x;
    g_esrc[p1] = s4.y;
    g_esrc[p2] = s4.z;
    g_esrc[p3] = s4.w;
}

// ---------------- K4: warp-per-node aggregation, unroll 8 (MLP=8) ------------------
__global__ void k_agg(const float* __restrict__ h) {
    if (blockIdx.x == 0) {
        int tt = threadIdx.x;
        if (tt < F_DIM) { g_colsum[tt] = 0.f; g_colsq[tt] = 0.f; }
        if (tt < NB) g_pkt[tt] = 0u;
    }

    int warp = (blockIdx.x * blockDim.x + threadIdx.x) >> 5;
    int lane = threadIdx.x & 31;
    if (warp >= N_NODES) return;

    int start = g_off[warp];
    int d = g_deg[warp];
    int end = start + d;

    const ull* hl = (const ull*)h + lane;

    ull sum = 0ull;
    ull sq  = 0ull;
    float mx0 = -3.402823466e38f, mx1 = -3.402823466e38f;
    float mn0 =  3.402823466e38f, mn1 =  3.402823466e38f;

    int e = start;
    // align index stream to 16B
    while (e < end && (e & 3)) {
        ull va = hl[g_esrc[e] * 32];
        add2(sum, va); fma2(sq, va);
        mx0 = fmaxf(mx0, lo32(va)); mx1 = fmaxf(mx1, hi32(va));
        mn0 = fminf(mn0, lo32(va)); mn1 = fminf(mn1, hi32(va));
        e++;
    }
    // unroll 8: two int4 index loads, 8 outstanding gathers
    for (; e + 8 <= end; e += 8) {
        int4 sa = *(const int4*)(g_esrc + e);
        int4 sb = *(const int4*)(g_esrc + e + 4);
        ull v0 = hl[sa.x * 32];
        ull v1 = hl[sa.y * 32];
        ull v2 = hl[sa.z * 32];
        ull v3 = hl[sa.w * 32];
        ull v4 = hl[sb.x * 32];
        ull v5 = hl[sb.y * 32];
        ull v6 = hl[sb.z * 32];
        ull v7 = hl[sb.w * 32];
        add2(sum, v0); fma2(sq, v0);
        mx0 = fmaxf(mx0, lo32(v0)); mx1 = fmaxf(mx1, hi32(v0));
        mn0 = fminf(mn0, lo32(v0)); mn1 = fminf(mn1, hi32(v0));
        add2(sum, v1); fma2(sq, v1);
        mx0 = fmaxf(mx0, lo32(v1)); mx1 = fmaxf(mx1, hi32(v1));
        mn0 = fminf(mn0, lo32(v1)); mn1 = fminf(mn1, hi32(v1));
        add2(sum, v2); fma2(sq, v2);
        mx0 = fmaxf(mx0, lo32(v2)); mx1 = fmaxf(mx1, hi32(v2));
        mn0 = fminf(mn0, lo32(v2)); mn1 = fminf(mn1, hi32(v2));
        add2(sum, v3); fma2(sq, v3);
        mx0 = fmaxf(mx0, lo32(v3)); mx1 = fmaxf(mx1, hi32(v3));
        mn0 = fminf(mn0, lo32(v3)); mn1 = fminf(mn1, hi32(v3));
        add2(sum, v4); fma2(sq, v4);
        mx0 = fmaxf(mx0, lo32(v4)); mx1 = fmaxf(mx1, hi32(v4));
        mn0 = fminf(mn0, lo32(v4)); mn1 = fminf(mn1, hi32(v4));
        add2(sum, v5); fma2(sq, v5);
        mx0 = fmaxf(mx0, lo32(v5)); mx1 = fmaxf(mx1, hi32(v5));
        mn0 = fminf(mn0, lo32(v5)); mn1 = fminf(mn1, hi32(v5));
        add2(sum, v6); fma2(sq, v6);
        mx0 = fmaxf(mx0, lo32(v6)); mx1 = fmaxf(mx1, hi32(v6));
        mn0 = fminf(mn0, lo32(v6)); mn1 = fminf(mn1, hi32(v6));
        add2(sum, v7); fma2(sq, v7);
        mx0 = fmaxf(mx0, lo32(v7)); mx1 = fmaxf(mx1, hi32(v7));
        mn0 = fminf(mn0, lo32(v7)); mn1 = fminf(mn1, hi32(v7));
    }
    for (; e + 4 <= end; e += 4) {
        int4 sa = *(const int4*)(g_esrc + e);
        ull v0 = hl[sa.x * 32];
        ull v1 = hl[sa.y * 32];
        ull v2 = hl[sa.z * 32];
        ull v3 = hl[sa.w * 32];
        add2(sum, v0); fma2(sq, v0);
        mx0 = fmaxf(mx0, lo32(v0)); mx1 = fmaxf(mx1, hi32(v0));
        mn0 = fminf(mn0, lo32(v0)); mn1 = fminf(mn1, hi32(v0));
        add2(sum, v1); fma2(sq, v1);
        mx0 = fmaxf(mx0, lo32(v1)); mx1 = fmaxf(mx1, hi32(v1));
        mn0 = fminf(mn0, lo32(v1)); mn1 = fminf(mn1, hi32(v1));
        add2(sum, v2); fma2(sq, v2);
        mx0 = fmaxf(mx0, lo32(v2)); mx1 = fmaxf(mx1, hi32(v2));
        mn0 = fminf(mn0, lo32(v2)); mn1 = fminf(mn1, hi32(v2));
        add2(sum, v3); fma2(sq, v3);
        mx0 = fmaxf(mx0, lo32(v3)); mx1 = fmaxf(mx1, hi32(v3));
        mn0 = fminf(mn0, lo32(v3)); mn1 = fminf(mn1, hi32(v3));
    }
    for (; e < end; e++) {
        ull va = hl[g_esrc[e] * 32];
        add2(sum, va); fma2(sq, va);
        mx0 = fmaxf(mx0, lo32(va)); mx1 = fmaxf(mx1, hi32(va));
        mn0 = fminf(mn0, lo32(va)); mn1 = fminf(mn1, hi32(va));
    }

    unsigned* ar = g_a16 + (size_t)warp * 128 + lane;
    if (d > 0) {
        float inv = 1.0f / (float)d;
        float s0 = lo32(sum), s1 = hi32(sum);
        float q0 = lo32(sq),  q1 = hi32(sq);
        float mean0 = s0 * inv, mean1 = s1 * inv;
        float var0 = fmaxf(q0 * inv - mean0 * mean0, 0.f);
        float var1 = fmaxf(q1 * inv - mean1 * mean1, 0.f);
        float std0 = sqrtf(var0 + EPS_STD);
        float std1 = sqrtf(var1 + EPS_STD);
        // sections: 0=mean 1=max 2=min 3=std; 32 fp16x2 words each
        ar[0]  = packh(mean0, mean1);
        ar[32] = packh(mx0, mx1);
        ar[64] = packh(mn0, mn1);
        ar[96] = packh(std0, std1);
        if (lane == 0) {
            float logD = logf((float)d + 1.0f);
            g_c1[warp] = logD / AVG_D_LOG;
            g_c2[warp] = AVG_D_LOG / fmaxf(logD, 1e-12f);
        }
    } else {
        ar[0] = 0u; ar[32] = 0u; ar[64] = 0u; ar[96] = 0u;
        if (lane == 0) { g_c1[warp] = 0.f; g_c2[warp] = 0.f; }
    }
    if (lane == 0) g_deg[warp] = 0;
}

// ---------------- K5: mma.sync fp16 GEMM, double-buffered cp.async pipeline --------
#define AST 144
#define SBUF  (64 * AST)              // 9216
#define SB_OFF (128 * AST)            // 18432 (A region size)
#define BUFSZ (SB_OFF + 3 * SBUF)     // 46080 per buffer
#define SMEM_MM (2 * BUFSZ)           // 92160

__global__ void __launch_bounds__(256)
k_gemm_mma(const float* __restrict__ bias) {
    extern __shared__ char smem[];
    const uint32_t sb = smem_u32(smem);
    int t = threadIdx.x;
    int w = t >> 5;
    int lane = t & 31;
    int m0 = blockIdx.x * 128;

    float acc[3][8][4];
    #pragma unroll
    for (int p = 0; p < 3; p++)
        #pragma unroll
        for (int nt = 0; nt < 8; nt++)
            #pragma unroll
            for (int j = 0; j < 4; j++) acc[p][nt][j] = 0.f;

    const int arow = t >> 3;
    const int ag   = t & 7;

    auto load_chunk = [&](int c, uint32_t buf) {
        #pragma unroll
        for (int it = 0; it < 4; it++) {
            int row = arow + it * 32;
            int gm = m0 + row;
            unsigned ok = (gm < N_NODES) ? 16u : 0u;
            int gmc = (gm < N_NODES) ? gm : 0;
            cp16z(buf + row * AST + ag * 16,
                  g_a16 + (size_t)gmc * 128 + c * 32 + ag * 4, ok);
        }
        #pragma unroll
        for (int it = 0; it < 6; it++) {
            int idx = t + it * 256;
            int p = idx >> 9;
            int rem = idx & 511;
            int row = rem >> 3;
            int g = rem & 7;
            cp16z(buf + SB_OFF + p * SBUF + row * AST + g * 16,
                  g_whi + row * 768 + p * 256 + c * 64 + g * 8, 16u);
        }
        CP_COMMIT();
    };

    load_chunk(0, sb);

    for (int c = 0; c < 4; c++) {
        if (c < 3) {
            load_chunk(c + 1, sb + ((c + 1) & 1) * BUFSZ);
            CP_WAIT(1);
        } else {
            CP_WAIT(0);
        }
        __syncthreads();

        uint32_t buf = sb + (c & 1) * BUFSZ;

        #pragma unroll
        for (int ks = 0; ks < 4; ks++) {
            int ar = w * 16 + (lane & 15);
            uint32_t aoff = (uint32_t)(ar * AST + ks * 32 + ((lane >> 4) << 4));
            uint32_t a0, a1, a2, a3;
            ldsm4(a0, a1, a2, a3, buf + aoff);

            #pragma unroll
            for (int np = 0; np < 4; np++) {
                int nrow = np * 16 + (lane & 7) + ((lane & 16) ? 8 : 0);
                uint32_t boff = (uint32_t)(nrow * AST + ks * 32 + ((lane & 8) ? 16 : 0));
                #pragma unroll
                for (int p = 0; p < 3; p++) {
                    uint32_t b0, b1, b2, b3;
                    ldsm4(b0, b1, b2, b3, buf + SB_OFF + p * SBUF + boff);
                    mma_f16(acc[p][np * 2],     a0, a1, a2, a3, b0, b1);
                    mma_f16(acc[p][np * 2 + 1], a0, a1, a2, a3, b2, b3);
                }
            }
        }
        __syncthreads();
    }

    // ---- epilogue: x = D0 + c1*D1 + c2*D2 + bias; fused BN column stats ----
    float* swsum = (float*)smem;
    float* swsq  = (float*)(smem + 2048);

    int rowA = m0 + w * 16 + (lane >> 2);
    int rowB = rowA + 8;
    bool va = rowA < N_NODES, vb = rowB < N_NODES;
    float c1a = 0.f, c2a = 0.f, c1b = 0.f, c2b = 0.f;
    if (va) { c1a = g_c1[rowA]; c2a = g_c2[rowA]; }
    if (vb) { c1b = g_c1[rowB]; c2b = g_c2[rowB]; }

    #pragma unroll
    for (int nt = 0; nt < 8; nt++) {
        int col = nt * 8 + (lane & 3) * 2;
        float b0 = bias[col];
        float b1 = bias[col + 1];
        float x0a = acc[0][nt][0] + c1a * acc[1][nt][0] + c2a * acc[2][nt][0] + b0;
        float x1a = acc[0][nt][1] + c1a * acc[1][nt][1] + c2a * acc[2][nt][1] + b1;
        float x0b = acc[0][nt][2] + c1b * acc[1][nt][2] + c2b * acc[2][nt][2] + b0;
        float x1b = acc[0][nt][3] + c1b * acc[1][nt][3] + c2b * acc[2][nt][3] + b1;
        if (va) *(float2*)(g_x + (size_t)rowA * 64 + col) = make_float2(x0a, x1a);
        if (vb) *(float2*)(g_x + (size_t)rowB * 64 + col) = make_float2(x0b, x1b);

        float s0 = (va ? x0a : 0.f) + (vb ? x0b : 0.f);
        float s1 = (va ? x1a : 0.f) + (vb ? x1b : 0.f);
        float q0 = (va ? x0a * x0a : 0.f) + (vb ? x0b * x0b : 0.f);
        float q1 = (va ? x1a * x1a : 0.f) + (vb ? x1b * x1b : 0.f);
        #pragma unroll
        for (int o = 4; o <= 16; o <<= 1) {
            s0 += __shfl_xor_sync(0xffffffffu, s0, o);
            s1 += __shfl_xor_sync(0xffffffffu, s1, o);
            q0 += __shfl_xor_sync(0xffffffffu, q0, o);
            q1 += __shfl_xor_sync(0xffffffffu, q1, o);
        }
        if (lane < 4) {
            swsum[w * 64 + nt * 8 + lane * 2]     = s0;
            swsum[w * 64 + nt * 8 + lane * 2 + 1] = s1;
            swsq [w * 64 + nt * 8 + lane * 2]     = q0;
            swsq [w * 64 + nt * 8 + lane * 2 + 1] = q1;
        }
    }
    __syncthreads();
    if (t < 64) {
        float s = 0.f, q = 0.f;
        #pragma unroll
        for (int k = 0; k < 8; k++) {
            s += swsum[k * 64 + t];
            q += swsq[k * 64 + t];
        }
        atomicAdd(&g_colsum[t], s);
        atomicAdd(&g_colsq[t], q);
    }
}

// ---------------- K6: BN + ReLU + residual (float4) -------------------------------
__global__ void k_final(const float* __restrict__ h,
                        const float* __restrict__ gamma,
                        const float* __restrict__ beta,
                        float* __restrict__ out) {
    int i = blockIdx.x * blockDim.x + threadIdx.x;
    if (i >= N_NODES * F_DIM / 4) return;
    int j = (i & 15) * 4;
    const float invN = 1.0f / (float)N_NODES;
    float4 cs = *(const float4*)(g_colsum + j);
    float4 cq = *(const float4*)(g_colsq + j);
    float4 gm = *(const float4*)(gamma + j);
    float4 bt = *(const float4*)(beta + j);
    float4 xv = ((const float4*)g_x)[i];
    float4 hv = ((const float4*)h)[i];
    float4 r;
    {
        float mu = cs.x * invN;
        float inv = rsqrtf(cq.x * invN - mu * mu + EPS_BN);
        r.x = hv.x + fmaxf(gm.x * (xv.x - mu) * inv + bt.x, 0.f);
    }
    {
        float mu = cs.y * invN;
        float inv = rsqrtf(cq.y * invN - mu * mu + EPS_BN);
        r.y = hv.y + fmaxf(gm.y * (xv.y - mu) * inv + bt.y, 0.f);
    }
    {
        float mu = cs.z * invN;
        float inv = rsqrtf(cq.z * invN - mu * mu + EPS_BN);
        r.z = hv.z + fmaxf(gm.z * (xv.z - mu) * inv + bt.z, 0.f);
    }
    {
        float mu = cs.w * invN;
        float inv = rsqrtf(cq.w * invN - mu * mu + EPS_BN);
        r.w = hv.w + fmaxf(gm.w * (xv.w - mu) * inv + bt.w, 0.f);
    }
    ((float4*)out)[i] = r;
}

// ---------------- launch ------------------------------------------------------------
extern "C" void kernel_launch(void* const* d_in, const int* in_sizes, int n_in,
                              void* d_out, int out_size) {
    const float* h     = (const float*)d_in[0];
    const int*   src   = (const int*)d_in[1];
    const int*   dst   = (const int*)d_in[2];
    const float* W     = (const float*)d_in[3];
    const float* b     = (const float*)d_in[4];
    const float* gamma = (const float*)d_in[5];
    const float* beta  = (const float*)d_in[6];
    float* out = (float*)d_out;

    cudaFuncSetAttribute(k_gemm_mma, cudaFuncAttributeMaxDynamicSharedMemorySize, SMEM_MM);

    k_hist_wprep<<<(N_EDGES / 4 + 255) / 256, 256>>>(dst, W);
    k_scan<<<NB, 256>>>();
    k_scatter<<<(N_EDGES / 4 + 255) / 256, 256>>>(src, dst);
    k_agg<<<(N_NODES + 7) / 8, 256>>>(h);
    k_gemm_mma<<<(N_NODES + 127) / 128, 256, SMEM_MM>>>(b);
    k_final<<<(N_NODES * F_DIM / 4 + 255) / 256, 256>>>(h, gamma, beta, out);
}

// round 15
// speedup vs baseline: 1.0254x; 1.0254x over previous
#include <cuda_runtime.h>
#include <cuda_fp16.h>
#include <math.h>
#include <stdint.h>

#define N_NODES 50000
#define N_EDGES 800000
#define F_DIM   64
#define AVG_D_LOG 2.833f
#define EPS_STD 1e-5f
#define EPS_BN  1e-5f
#define NB 196   // ceil(50000/256)
#define A_FLAG 0x40000000u
#define P_FLAG 0x80000000u

typedef unsigned long long ull;

// ---------------- device scratch (all zero-initialized at load) ----------------
__device__ int   g_deg[N_NODES];       // zeroed by k_agg after use
__device__ int   g_off[N_NODES];
__device__ int   g_cursor[N_NODES];
__device__ int   g_esrc[N_EDGES];
__device__ unsigned g_pkt[NB];         // scan lookback state; zeroed by k_agg
__device__ unsigned g_a16[(size_t)N_NODES * 128];  // agg rows as fp16x2 words
__device__ float g_c1[N_NODES];
__device__ float g_c2[N_NODES];
__device__ float g_x[(size_t)N_NODES * F_DIM];
__device__ float g_colsum[F_DIM];
__device__ float g_colsq[F_DIM];
__device__ __half g_whi[64 * 768];     // W^T fp16 [n][k]

// ---------------- helpers -------------------------------------------------------
__device__ __forceinline__ uint32_t smem_u32(const void* p) {
    uint32_t r;
    asm("{ .reg .u64 t; cvta.to.shared.u64 t, %1; cvt.u32.u64 %0, t; }"
        : "=r"(r) : "l"(p));
    return r;
}
__device__ __forceinline__ void ldsm4(uint32_t& r0, uint32_t& r1,
                                      uint32_t& r2, uint32_t& r3, uint32_t a) {
    asm volatile("ldmatrix.sync.aligned.m8n8.x4.shared.b16 {%0,%1,%2,%3}, [%4];"
                 : "=r"(r0), "=r"(r1), "=r"(r2), "=r"(r3) : "r"(a));
}
__device__ __forceinline__ void mma_f16(float* d,
                                        uint32_t a0, uint32_t a1, uint32_t a2, uint32_t a3,
                                        uint32_t b0, uint32_t b1) {
    asm volatile(
        "mma.sync.aligned.m16n8k16.row.col.f32.f16.f16.f32 "
        "{%0,%1,%2,%3}, {%4,%5,%6,%7}, {%8,%9}, {%0,%1,%2,%3};"
        : "+f"(d[0]), "+f"(d[1]), "+f"(d[2]), "+f"(d[3])
        : "r"(a0), "r"(a1), "r"(a2), "r"(a3), "r"(b0), "r"(b1));
}
__device__ __forceinline__ uint32_t packh(float x, float y) {
    __half2 t;
    t.x = __float2half_rn(x);
    t.y = __float2half_rn(y);
    return *(uint32_t*)&t;
}
// cp.async 16B with zero-fill (src_bytes = 0 -> zfill, no read)
__device__ __forceinline__ void cp16z(uint32_t s, const void* g, unsigned srcbytes) {
    asm volatile(
        "{ .reg .u64 ga; cvta.to.global.u64 ga, %1;\n\t"
        "cp.async.cg.shared.global [%0], [ga], 16, %2; }"
        :: "r"(s), "l"(g), "r"(srcbytes) : "memory");
}
#define CP_COMMIT() asm volatile("cp.async.commit_group;" ::: "memory")
#define CP_WAIT(n)  asm volatile("cp.async.wait_group %0;" :: "n"(n) : "memory")
// packed f32x2 (add/fma only on this toolchain)
__device__ __forceinline__ void add2(ull& d, ull a) {
    asm("add.rn.f32x2 %0, %0, %1;" : "+l"(d) : "l"(a));
}
__device__ __forceinline__ void fma2(ull& d, ull a) {
    asm("fma.rn.f32x2 %0, %1, %1, %0;" : "+l"(d) : "l"(a));
}
__device__ __forceinline__ float lo32(ull v) { return __uint_as_float((unsigned)v); }
__device__ __forceinline__ float hi32(ull v) { return __uint_as_float((unsigned)(v >> 32)); }

// ---------------- K1: degree histogram (8 edges/thread) + W fp16 transpose --------
__global__ void k_hist_wprep(const int* __restrict__ dst, const float* __restrict__ W) {
    int t = blockIdx.x * blockDim.x + threadIdx.x;
    if (t < N_EDGES / 8) {
        int4 d4 = ((const int4*)dst)[2 * t];
        int4 d5 = ((const int4*)dst)[2 * t + 1];
        atomicAdd(&g_deg[d4.x], 1);
        atomicAdd(&g_deg[d4.y], 1);
        atomicAdd(&g_deg[d4.z], 1);
        atomicAdd(&g_deg[d4.w], 1);
        atomicAdd(&g_deg[d5.x], 1);
        atomicAdd(&g_deg[d5.y], 1);
        atomicAdd(&g_deg[d5.z], 1);
        atomicAdd(&g_deg[d5.w], 1);
    }
    if (t < 768 * 64) {
        int k = t >> 6;
        int n = t & 63;
        g_whi[n * 768 + k] = __float2half_rn(W[t]);
    }
}

// ---------------- K2: single-pass decoupled-lookback scan -------------------------
__global__ void k_scan(void) {
    __shared__ int s[256];
    __shared__ unsigned sprefix;
    int t = threadIdx.x;
    int bidx = blockIdx.x;
    int i = bidx * 256 + t;
    int v = (i < N_NODES) ? g_deg[i] : 0;
    s[t] = v;
    __syncthreads();
    #pragma unroll
    for (int off = 1; off < 256; off <<= 1) {
        int x = (t >= off) ? s[t - off] : 0;
        __syncthreads();
        s[t] += x;
        __syncthreads();
    }
    int total = s[255];

    if (t == 0) {
        unsigned pub = (bidx == 0) ? (P_FLAG | (unsigned)total)
                                   : (A_FLAG | (unsigned)total);
        atomicExch(&g_pkt[bidx], pub);
        if (bidx == 0) sprefix = 0;
    }

    if (bidx > 0 && t < 32) {
        unsigned running = 0;
        int idx = bidx - 1;
        for (;;) {
            int j = idx - t;
            unsigned p;
            if (j >= 0) {
                do { p = ((volatile unsigned*)g_pkt)[j]; } while (p == 0);
            } else {
                p = P_FLAG;
            }
            unsigned pm = __ballot_sync(0xffffffffu, (p & P_FLAG) != 0);
            unsigned val = p & 0x3fffffffu;
            if (pm) {
                int k = __ffs(pm) - 1;
                unsigned contrib = (t <= k) ? val : 0;
                #pragma unroll
                for (int o = 16; o > 0; o >>= 1)
                    contrib += __shfl_down_sync(0xffffffffu, contrib, o);
                if (t == 0) sprefix = running + contrib;
                break;
            } else {
                unsigned contrib = (j >= 0) ? val : 0;
                #pragma unroll
                for (int o = 16; o > 0; o >>= 1)
                    contrib += __shfl_down_sync(0xffffffffu, contrib, o);
                running += __shfl_sync(0xffffffffu, contrib, 0);
                idx -= 32;
            }
        }
        if (t == 0)
            atomicExch(&g_pkt[bidx], P_FLAG | (sprefix + (unsigned)total));
    }
    __syncthreads();

    if (i < N_NODES) {
        int ex = (int)sprefix + s[t] - v;
        g_off[i] = ex;
        g_cursor[i] = ex;
    }
}

// ---------------- K3: scatter edges, 8 per thread (MLP=8) -------------------------
__global__ void k_scatter(const int* __restrict__ src, const int* __restrict__ dst) {
    int t = blockIdx.x * blockDim.x + threadIdx.x;
    if (t >= N_EDGES / 8) return;
    int4 d4 = ((const int4*)dst)[2 * t];
    int4 d5 = ((const int4*)dst)[2 * t + 1];
    int4 s4 = ((const int4*)src)[2 * t];
    int4 s5 = ((const int4*)src)[2 * t + 1];
    int p0 = atomicAdd(&g_cursor[d4.x], 1);
    int p1 = atomicAdd(&g_cursor[d4.y], 1);
    int p2 = atomicAdd(&g_cursor[d4.z], 1);
    int p3 = atomicAdd(&g_cursor[d4.w], 1);
    int p4 = atomicAdd(&g_cursor[d5.x], 1);
    int p5 = atomicAdd(&g_cursor[d5.y], 1);
    int p6 = atomicAdd(&g_cursor[d5.z], 1);
    int p7 = atomicAdd(&g_cursor[d5.w], 1);
    g_esrc[p0] = s4.x;
    g_esrc[p1] = s4.y;
    g_esrc[p2] = s4.z;
    g_esrc[p3] = s4.w;
    g_esrc[p4] = s5.x;
    g_esrc[p5] = s5.y;
    g_esrc[p6] = s5.z;
    g_esrc[p7] = s5.w;
}

// ---------------- K4: warp-per-node aggregation (R13 exact: unroll 4, regs=32) ----
__global__ void k_agg(const float* __restrict__ h) {
    if (blockIdx.x == 0) {
        int tt = threadIdx.x;
        if (tt < F_DIM) { g_colsum[tt] = 0.f; g_colsq[tt] = 0.f; }
        if (tt < NB) g_pkt[tt] = 0u;
    }

    int warp = (blockIdx.x * blockDim.x + threadIdx.x) >> 5;
    int lane = threadIdx.x & 31;
    if (warp >= N_NODES) return;

    int start = g_off[warp];
    int d = g_deg[warp];
    int end = start + d;

    const ull* hl = (const ull*)h + lane;

    ull sum = 0ull;
    ull sq  = 0ull;
    float mx0 = -3.402823466e38f, mx1 = -3.402823466e38f;
    float mn0 =  3.402823466e38f, mn1 =  3.402823466e38f;

    int e = start;
    while (e < end && (e & 3)) {
        ull va = hl[g_esrc[e] * 32];
        add2(sum, va); fma2(sq, va);
        mx0 = fmaxf(mx0, lo32(va)); mx1 = fmaxf(mx1, hi32(va));
        mn0 = fminf(mn0, lo32(va)); mn1 = fminf(mn1, hi32(va));
        e++;
    }
    for (; e + 4 <= end; e += 4) {
        int4 s4 = *(const int4*)(g_esrc + e);
        ull va = hl[s4.x * 32];
        ull vb = hl[s4.y * 32];
        ull vc = hl[s4.z * 32];
        ull vd = hl[s4.w * 32];
        add2(sum, va); fma2(sq, va);
        mx0 = fmaxf(mx0, lo32(va)); mx1 = fmaxf(mx1, hi32(va));
        mn0 = fminf(mn0, lo32(va)); mn1 = fminf(mn1, hi32(va));
        add2(sum, vb); fma2(sq, vb);
        mx0 = fmaxf(mx0, lo32(vb)); mx1 = fmaxf(mx1, hi32(vb));
        mn0 = fminf(mn0, lo32(vb)); mn1 = fminf(mn1, hi32(vb));
        add2(sum, vc); fma2(sq, vc);
        mx0 = fmaxf(mx0, lo32(vc)); mx1 = fmaxf(mx1, hi32(vc));
        mn0 = fminf(mn0, lo32(vc)); mn1 = fminf(mn1, hi32(vc));
        add2(sum, vd); fma2(sq, vd);
        mx0 = fmaxf(mx0, lo32(vd)); mx1 = fmaxf(mx1, hi32(vd));
        mn0 = fminf(mn0, lo32(vd)); mn1 = fminf(mn1, hi32(vd));
    }
    for (; e < end; e++) {
        ull va = hl[g_esrc[e] * 32];
        add2(sum, va); fma2(sq, va);
        mx0 = fmaxf(mx0, lo32(va)); mx1 = fmaxf(mx1, hi32(va));
        mn0 = fminf(mn0, lo32(va)); mn1 = fminf(mn1, hi32(va));
    }

    unsigned* ar = g_a16 + (size_t)warp * 128 + lane;
    if (d > 0) {
        float inv = 1.0f / (float)d;
        float s0 = lo32(sum), s1 = hi32(sum);
        float q0 = lo32(sq),  q1 = hi32(sq);
        float mean0 = s0 * inv, mean1 = s1 * inv;
        float var0 = fmaxf(q0 * inv - mean0 * mean0, 0.f);
        float var1 = fmaxf(q1 * inv - mean1 * mean1, 0.f);
        float std0 = sqrtf(var0 + EPS_STD);
        float std1 = sqrtf(var1 + EPS_STD);
        // sections: 0=mean 1=max 2=min 3=std; 32 fp16x2 words each
        ar[0]  = packh(mean0, mean1);
        ar[32] = packh(mx0, mx1);
        ar[64] = packh(mn0, mn1);
        ar[96] = packh(std0, std1);
        if (lane == 0) {
            float logD = logf((float)d + 1.0f);
            g_c1[warp] = logD / AVG_D_LOG;
            g_c2[warp] = AVG_D_LOG / fmaxf(logD, 1e-12f);
        }
    } else {
        ar[0] = 0u; ar[32] = 0u; ar[64] = 0u; ar[96] = 0u;
        if (lane == 0) { g_c1[warp] = 0.f; g_c2[warp] = 0.f; }
    }
    if (lane == 0) g_deg[warp] = 0;
}

// ---------------- K5: mma.sync fp16 GEMM, double-buffered cp.async pipeline --------
#define AST 144
#define SBUF  (64 * AST)              // 9216
#define SB_OFF (128 * AST)            // 18432 (A region size)
#define BUFSZ (SB_OFF + 3 * SBUF)     // 46080 per buffer
#define SMEM_MM (2 * BUFSZ)           // 92160

__global__ void __launch_bounds__(256)
k_gemm_mma(const float* __restrict__ bias) {
    extern __shared__ char smem[];
    const uint32_t sb = smem_u32(smem);
    int t = threadIdx.x;
    int w = t >> 5;
    int lane = t & 31;
    int m0 = blockIdx.x * 128;

    float acc[3][8][4];
    #pragma unroll
    for (int p = 0; p < 3; p++)
        #pragma unroll
        for (int nt = 0; nt < 8; nt++)
            #pragma unroll
            for (int j = 0; j < 4; j++) acc[p][nt][j] = 0.f;

    const int arow = t >> 3;
    const int ag   = t & 7;

    auto load_chunk = [&](int c, uint32_t buf) {
        #pragma unroll
        for (int it = 0; it < 4; it++) {
            int row = arow + it * 32;
            int gm = m0 + row;
            unsigned ok = (gm < N_NODES) ? 16u : 0u;
            int gmc = (gm < N_NODES) ? gm : 0;
            cp16z(buf + row * AST + ag * 16,
                  g_a16 + (size_t)gmc * 128 + c * 32 + ag * 4, ok);
        }
        #pragma unroll
        for (int it = 0; it < 6; it++) {
            int idx = t + it * 256;
            int p = idx >> 9;
            int rem = idx & 511;
            int row = rem >> 3;
            int g = rem & 7;
            cp16z(buf + SB_OFF + p * SBUF + row * AST + g * 16,
                  g_whi + row * 768 + p * 256 + c * 64 + g * 8, 16u);
        }
        CP_COMMIT();
    };

    load_chunk(0, sb);

    for (int c = 0; c < 4; c++) {
        if (c < 3) {
            load_chunk(c + 1, sb + ((c + 1) & 1) * BUFSZ);
            CP_WAIT(1);
        } else {
            CP_WAIT(0);
        }
        __syncthreads();

        uint32_t buf = sb + (c & 1) * BUFSZ;

        #pragma unroll
        for (int ks = 0; ks < 4; ks++) {
            int ar = w * 16 + (lane & 15);
            uint32_t aoff = (uint32_t)(ar * AST + ks * 32 + ((lane >> 4) << 4));
            uint32_t a0, a1, a2, a3;
            ldsm4(a0, a1, a2, a3, buf + aoff);

            #pragma unroll
            for (int np = 0; np < 4; np++) {
                int nrow = np * 16 + (lane & 7) + ((lane & 16) ? 8 : 0);
                uint32_t boff = (uint32_t)(nrow * AST + ks * 32 + ((lane & 8) ? 16 : 0));
                #pragma unroll
                for (int p = 0; p < 3; p++) {
                    uint32_t b0, b1, b2, b3;
                    ldsm4(b0, b1, b2, b3, buf + SB_OFF + p * SBUF + boff);
                    mma_f16(acc[p][np * 2],     a0, a1, a2, a3, b0, b1);
                    mma_f16(acc[p][np * 2 + 1], a0, a1, a2, a3, b2, b3);
                }
            }
        }
        __syncthreads();
    }

    // ---- epilogue: x = D0 + c1*D1 + c2*D2 + bias; fused BN column stats ----
    float* swsum = (float*)smem;
    float* swsq  = (float*)(smem + 2048);

    int rowA = m0 + w * 16 + (lane >> 2);
    int rowB = rowA + 8;
    bool va = rowA < N_NODES, vb = rowB < N_NODES;
    float c1a = 0.f, c2a = 0.f, c1b = 0.f, c2b = 0.f;
    if (va) { c1a = g_c1[rowA]; c2a = g_c2[rowA]; }
    if (vb) { c1b = g_c1[rowB]; c2b = g_c2[rowB]; }

    #pragma unroll
    for (int nt = 0; nt < 8; nt++) {
        int col = nt * 8 + (lane & 3) * 2;
        float b0 = bias[col];
        float b1 = bias[col + 1];
        float x0a = acc[0][nt][0] + c1a * acc[1][nt][0] + c2a * acc[2][nt][0] + b0;
        float x1a = acc[0][nt][1] + c1a * acc[1][nt][1] + c2a * acc[2][nt][1] + b1;
        float x0b = acc[0][nt][2] + c1b * acc[1][nt][2] + c2b * acc[2][nt][2] + b0;
        float x1b = acc[0][nt][3] + c1b * acc[1][nt][3] + c2b * acc[2][nt][3] + b1;
        if (va) *(float2*)(g_x + (size_t)rowA * 64 + col) = make_float2(x0a, x1a);
        if (vb) *(float2*)(g_x + (size_t)rowB * 64 + col) = make_float2(x0b, x1b);

        float s0 = (va ? x0a : 0.f) + (vb ? x0b : 0.f);
        float s1 = (va ? x1a : 0.f) + (vb ? x1b : 0.f);
        float q0 = (va ? x0a * x0a : 0.f) + (vb ? x0b * x0b : 0.f);
        float q1 = (va ? x1a * x1a : 0.f) + (vb ? x1b * x1b : 0.f);
        #pragma unroll
        for (int o = 4; o <= 16; o <<= 1) {
            s0 += __shfl_xor_sync(0xffffffffu, s0, o);
            s1 += __shfl_xor_sync(0xffffffffu, s1, o);
            q0 += __shfl_xor_sync(0xffffffffu, q0, o);
            q1 += __shfl_xor_sync(0xffffffffu, q1, o);
        }
        if (lane < 4) {
            swsum[w * 64 + nt * 8 + lane * 2]     = s0;
            swsum[w * 64 + nt * 8 + lane * 2 + 1] = s1;
            swsq [w * 64 + nt * 8 + lane * 2]     = q0;
            swsq [w * 64 + nt * 8 + lane * 2 + 1] = q1;
        }
    }
    __syncthreads();
    if (t < 64) {
        float s = 0.f, q = 0.f;
        #pragma unroll
        for (int k = 0; k < 8; k++) {
            s += swsum[k * 64 + t];
            q += swsq[k * 64 + t];
        }
        atomicAdd(&g_colsum[t], s);
        atomicAdd(&g_colsq[t], q);
    }
}

// ---------------- K6: BN + ReLU + residual (float4) -------------------------------
__global__ void k_final(const float* __restrict__ h,
                        const float* __restrict__ gamma,
                        const float* __restrict__ beta,
                        float* __restrict__ out) {
    int i = blockIdx.x * blockDim.x + threadIdx.x;
    if (i >= N_NODES * F_DIM / 4) return;
    int j = (i & 15) * 4;
    const float invN = 1.0f / (float)N_NODES;
    float4 cs = *(const float4*)(g_colsum + j);
    float4 cq = *(const float4*)(g_colsq + j);
    float4 gm = *(const float4*)(gamma + j);
    float4 bt = *(const float4*)(beta + j);
    float4 xv = ((const float4*)g_x)[i];
    float4 hv = ((const float4*)h)[i];
    float4 r;
    {
        float mu = cs.x * invN;
        float inv = rsqrtf(cq.x * invN - mu * mu + EPS_BN);
        r.x = hv.x + fmaxf(gm.x * (xv.x - mu) * inv + bt.x, 0.f);
    }
    {
        float mu = cs.y * invN;
        float inv = rsqrtf(cq.y * invN - mu * mu + EPS_BN);
        r.y = hv.y + fmaxf(gm.y * (xv.y - mu) * inv + bt.y, 0.f);
    }
    {
        float mu = cs.z * invN;
        float inv = rsqrtf(cq.z * invN - mu * mu + EPS_BN);
        r.z = hv.z + fmaxf(gm.z * (xv.z - mu) * inv + bt.z, 0.f);
    }
    {
        float mu = cs.w * invN;
        float inv = rsqrtf(cq.w * invN - mu * mu + EPS_BN);
        r.w = hv.w + fmaxf(gm.w * (xv.w - mu) * inv + bt.w, 0.f);
    }
    ((float4*)out)[i] = r;
}

// ---------------- launch ------------------------------------------------------------
extern "C" void kernel_launch(void* const* d_in, const int* in_sizes, int n_in,
                              void* d_out, int out_size) {
    const float* h     = (const float*)d_in[0];
    const int*   src   = (const int*)d_in[1];
    const int*   dst   = (const int*)d_in[2];
    const float* W     = (const float*)d_in[3];
    const float* b     = (const float*)d_in[4];
    const float* gamma = (const float*)d_in[5];
    const float* beta  = (const float*)d_in[6];
    float* out = (float*)d_out;

    cudaFuncSetAttribute(k_gemm_mma, cudaFuncAttributeMaxDynamicSharedMemorySize, SMEM_MM);

    k_hist_wprep<<<(N_EDGES / 8 + 255) / 256, 256>>>(dst, W);
    k_scan<<<NB, 256>>>();
    k_scatter<<<(N_EDGES / 8 + 255) / 256, 256>>>(src, dst);
    k_agg<<<(N_NODES + 7) / 8, 256>>>(h);
    k_gemm_mma<<<(N_NODES + 127) / 128, 256, SMEM_MM>>>(b);
    k_final<<<(N_NODES * F_DIM / 4 + 255) / 256, 256>>>(h, gamma, beta, out);
}

// round 16
// speedup vs baseline: 1.0551x; 1.0290x over previous
#include <cuda_runtime.h>
#include <cuda_fp16.h>
#include <math.h>
#include <stdint.h>

#define N_NODES 50000
#define N_EDGES 800000
#define F_DIM   64
#define AVG_D_LOG 2.833f
#define EPS_STD 1e-5f
#define EPS_BN  1e-5f
#define NB 196   // ceil(50000/256)
#define A_FLAG 0x40000000u
#define P_FLAG 0x80000000u

typedef unsigned long long ull;

// ---------------- device scratch (all zero-initialized at load) ----------------
__device__ int   g_deg[N_NODES];       // zeroed by k_agg after use
__device__ int   g_off[N_NODES];
__device__ int   g_cursor[N_NODES];
__device__ int   g_esrc[N_EDGES];
__device__ unsigned g_pkt[NB];         // scan lookback state; zeroed by k_agg
__device__ unsigned g_a16[(size_t)N_NODES * 128];  // agg rows as fp16x2 words
__device__ float g_c1[N_NODES];
__device__ float g_c2[N_NODES];
__device__ float g_x[(size_t)N_NODES * F_DIM];
__device__ float g_colsum[F_DIM];
__device__ float g_colsq[F_DIM];
__device__ __half g_whi[64 * 768];     // W^T fp16 [n][k]

// ---------------- helpers -------------------------------------------------------
__device__ __forceinline__ uint32_t smem_u32(const void* p) {
    uint32_t r;
    asm("{ .reg .u64 t; cvta.to.shared.u64 t, %1; cvt.u32.u64 %0, t; }"
        : "=r"(r) : "l"(p));
    return r;
}
__device__ __forceinline__ void ldsm4(uint32_t& r0, uint32_t& r1,
                                      uint32_t& r2, uint32_t& r3, uint32_t a) {
    asm volatile("ldmatrix.sync.aligned.m8n8.x4.shared.b16 {%0,%1,%2,%3}, [%4];"
                 : "=r"(r0), "=r"(r1), "=r"(r2), "=r"(r3) : "r"(a));
}
__device__ __forceinline__ void mma_f16(float* d,
                                        uint32_t a0, uint32_t a1, uint32_t a2, uint32_t a3,
                                        uint32_t b0, uint32_t b1) {
    asm volatile(
        "mma.sync.aligned.m16n8k16.row.col.f32.f16.f16.f32 "
        "{%0,%1,%2,%3}, {%4,%5,%6,%7}, {%8,%9}, {%0,%1,%2,%3};"
        : "+f"(d[0]), "+f"(d[1]), "+f"(d[2]), "+f"(d[3])
        : "r"(a0), "r"(a1), "r"(a2), "r"(a3), "r"(b0), "r"(b1));
}
__device__ __forceinline__ uint32_t packh(float x, float y) {
    __half2 t;
    t.x = __float2half_rn(x);
    t.y = __float2half_rn(y);
    return *(uint32_t*)&t;
}
// cp.async 16B with zero-fill (src_bytes = 0 -> zfill, no read)
__device__ __forceinline__ void cp16z(uint32_t s, const void* g, unsigned srcbytes) {
    asm volatile(
        "{ .reg .u64 ga; cvta.to.global.u64 ga, %1;\n\t"
        "cp.async.cg.shared.global [%0], [ga], 16, %2; }"
        :: "r"(s), "l"(g), "r"(srcbytes) : "memory");
}
#define CP_COMMIT() asm volatile("cp.async.commit_group;" ::: "memory")
#define CP_WAIT(n)  asm volatile("cp.async.wait_group %0;" :: "n"(n) : "memory")
// packed f32x2 (add/fma only on this toolchain)
__device__ __forceinline__ void add2(ull& d, ull a) {
    asm("add.rn.f32x2 %0, %0, %1;" : "+l"(d) : "l"(a));
}
__device__ __forceinline__ void fma2(ull& d, ull a) {
    asm("fma.rn.f32x2 %0, %1, %1, %0;" : "+l"(d) : "l"(a));
}
__device__ __forceinline__ float lo32(ull v) { return __uint_as_float((unsigned)v); }
__device__ __forceinline__ float hi32(ull v) { return __uint_as_float((unsigned)(v >> 32)); }
// packed fp16x2 convert + min/max (rounding is monotonic -> results bit-identical
// to fp32 min/max followed by fp16 rounding)
__device__ __forceinline__ uint32_t cvt_h2(ull v) {
    uint32_t r;
    asm("cvt.rn.f16x2.f32 %0, %1, %2;" : "=r"(r) : "f"(hi32(v)), "f"(lo32(v)));
    return r;
}
__device__ __forceinline__ void maxh2(uint32_t& d, uint32_t a) {
    asm("max.f16x2 %0, %0, %1;" : "+r"(d) : "r"(a));
}
__device__ __forceinline__ void minh2(uint32_t& d, uint32_t a) {
    asm("min.f16x2 %0, %0, %1;" : "+r"(d) : "r"(a));
}

// ---------------- K1: degree histogram (int4) + W fp16 transpose ------------------
__global__ void k_hist_wprep(const int* __restrict__ dst, const float* __restrict__ W) {
    int t = blockIdx.x * blockDim.x + threadIdx.x;
    if (t < N_EDGES / 4) {
        int4 d4 = ((const int4*)dst)[t];
        atomicAdd(&g_deg[d4.x], 1);
        atomicAdd(&g_deg[d4.y], 1);
        atomicAdd(&g_deg[d4.z], 1);
        atomicAdd(&g_deg[d4.w], 1);
    }
    if (t < 768 * 64) {
        int k = t >> 6;
        int n = t & 63;
        g_whi[n * 768 + k] = __float2half_rn(W[t]);
    }
}

// ---------------- K2: single-pass decoupled-lookback scan -------------------------
__global__ void k_scan(void) {
    __shared__ int s[256];
    __shared__ unsigned sprefix;
    int t = threadIdx.x;
    int bidx = blockIdx.x;
    int i = bidx * 256 + t;
    int v = (i < N_NODES) ? g_deg[i] : 0;
    s[t] = v;
    __syncthreads();
    #pragma unroll
    for (int off = 1; off < 256; off <<= 1) {
        int x = (t >= off) ? s[t - off] : 0;
        __syncthreads();
        s[t] += x;
        __syncthreads();
    }
    int total = s[255];

    if (t == 0) {
        unsigned pub = (bidx == 0) ? (P_FLAG | (unsigned)total)
                                   : (A_FLAG | (unsigned)total);
        atomicExch(&g_pkt[bidx], pub);
        if (bidx == 0) sprefix = 0;
    }

    if (bidx > 0 && t < 32) {
        unsigned running = 0;
        int idx = bidx - 1;
        for (;;) {
            int j = idx - t;
            unsigned p;
            if (j >= 0) {
                do { p = ((volatile unsigned*)g_pkt)[j]; } while (p == 0);
            } else {
                p = P_FLAG;
            }
            unsigned pm = __ballot_sync(0xffffffffu, (p & P_FLAG) != 0);
            unsigned val = p & 0x3fffffffu;
            if (pm) {
                int k = __ffs(pm) - 1;
                unsigned contrib = (t <= k) ? val : 0;
                #pragma unroll
                for (int o = 16; o > 0; o >>= 1)
                    contrib += __shfl_down_sync(0xffffffffu, contrib, o);
                if (t == 0) sprefix = running + contrib;
                break;
            } else {
                unsigned contrib = (j >= 0) ? val : 0;
                #pragma unroll
                for (int o = 16; o > 0; o >>= 1)
                    contrib += __shfl_down_sync(0xffffffffu, contrib, o);
                running += __shfl_sync(0xffffffffu, contrib, 0);
                idx -= 32;
            }
        }
        if (t == 0)
            atomicExch(&g_pkt[bidx], P_FLAG | (sprefix + (unsigned)total));
    }
    __syncthreads();

    if (i < N_NODES) {
        int ex = (int)sprefix + s[t] - v;
        g_off[i] = ex;
        g_cursor[i] = ex;
    }
}

// ---------------- K3: scatter edges, 4 per thread (MLP=4) -------------------------
__global__ void k_scatter(const int* __restrict__ src, const int* __restrict__ dst) {
    int t = blockIdx.x * blockDim.x + threadIdx.x;
    if (t >= N_EDGES / 4) return;
    int4 d4 = ((const int4*)dst)[t];
    int4 s4 = ((const int4*)src)[t];
    int p0 = atomicAdd(&g_cursor[d4.x], 1);
    int p1 = atomicAdd(&g_cursor[d4.y], 1);
    int p2 = atomicAdd(&g_cursor[d4.z], 1);
    int p3 = atomicAdd(&g_cursor[d4.w], 1);
    g_esrc[p0] = s4.x;
    g_esrc[p1] = s4.y;
    g_esrc[p2] = s4.z;
    g_esrc[p3] = s4.w;
}

// ---------------- K4: warp-per-node aggregation, f16x2 min/max --------------------
__global__ void k_agg(const float* __restrict__ h) {
    if (blockIdx.x == 0) {
        int tt = threadIdx.x;
        if (tt < F_DIM) { g_colsum[tt] = 0.f; g_colsq[tt] = 0.f; }
        if (tt < NB) g_pkt[tt] = 0u;
    }

    int warp = (blockIdx.x * blockDim.x + threadIdx.x) >> 5;
    int lane = threadIdx.x & 31;
    if (warp >= N_NODES) return;

    int start = g_off[warp];
    int d = g_deg[warp];
    int end = start + d;

    const ull* hl = (const ull*)h + lane;

    ull sum = 0ull;
    ull sq  = 0ull;
    uint32_t mx = 0xFBFFFBFFu;   // f16x2(-65504, -65504)
    uint32_t mn = 0x7BFF7BFFu;   // f16x2(+65504, +65504)

    int e = start;
    while (e < end && (e & 3)) {
        ull va = hl[g_esrc[e] * 32];
        add2(sum, va); fma2(sq, va);
        uint32_t vh = cvt_h2(va);
        maxh2(mx, vh); minh2(mn, vh);
        e++;
    }
    for (; e + 4 <= end; e += 4) {
        int4 s4 = *(const int4*)(g_esrc + e);
        ull va = hl[s4.x * 32];
        ull vb = hl[s4.y * 32];
        ull vc = hl[s4.z * 32];
        ull vd = hl[s4.w * 32];
        add2(sum, va); fma2(sq, va);
        { uint32_t vh = cvt_h2(va); maxh2(mx, vh); minh2(mn, vh); }
        add2(sum, vb); fma2(sq, vb);
        { uint32_t vh = cvt_h2(vb); maxh2(mx, vh); minh2(mn, vh); }
        add2(sum, vc); fma2(sq, vc);
        { uint32_t vh = cvt_h2(vc); maxh2(mx, vh); minh2(mn, vh); }
        add2(sum, vd); fma2(sq, vd);
        { uint32_t vh = cvt_h2(vd); maxh2(mx, vh); minh2(mn, vh); }
    }
    for (; e < end; e++) {
        ull va = hl[g_esrc[e] * 32];
        add2(sum, va); fma2(sq, va);
        uint32_t vh = cvt_h2(va);
        maxh2(mx, vh); minh2(mn, vh);
    }

    unsigned* ar = g_a16 + (size_t)warp * 128 + lane;
    if (d > 0) {
        float inv = 1.0f / (float)d;
        float s0 = lo32(sum), s1 = hi32(sum);
        float q0 = lo32(sq),  q1 = hi32(sq);
        float mean0 = s0 * inv, mean1 = s1 * inv;
        float var0 = fmaxf(q0 * inv - mean0 * mean0, 0.f);
        float var1 = fmaxf(q1 * inv - mean1 * mean1, 0.f);
        float std0 = sqrtf(var0 + EPS_STD);
        float std1 = sqrtf(var1 + EPS_STD);
        // sections: 0=mean 1=max 2=min 3=std; 32 fp16x2 words each
        ar[0]  = packh(mean0, mean1);
        ar[32] = mx;   // already packed f16x2
        ar[64] = mn;
        ar[96] = packh(std0, std1);
        if (lane == 0) {
            float logD = logf((float)d + 1.0f);
            g_c1[warp] = logD / AVG_D_LOG;
            g_c2[warp] = AVG_D_LOG / fmaxf(logD, 1e-12f);
        }
    } else {
        ar[0] = 0u; ar[32] = 0u; ar[64] = 0u; ar[96] = 0u;
        if (lane == 0) { g_c1[warp] = 0.f; g_c2[warp] = 0.f; }
    }
    if (lane == 0) g_deg[warp] = 0;
}

// ---------------- K5: mma.sync fp16 GEMM, double-buffered cp.async pipeline --------
#define AST 144
#define SBUF  (64 * AST)              // 9216
#define SB_OFF (128 * AST)            // 18432 (A region size)
#define BUFSZ (SB_OFF + 3 * SBUF)     // 46080 per buffer
#define SMEM_MM (2 * BUFSZ)           // 92160

__global__ void __launch_bounds__(256)
k_gemm_mma(const float* __restrict__ bias) {
    extern __shared__ char smem[];
    const uint32_t sb = smem_u32(smem);
    int t = threadIdx.x;
    int w = t >> 5;
    int lane = t & 31;
    int m0 = blockIdx.x * 128;

    float acc[3][8][4];
    #pragma unroll
    for (int p = 0; p < 3; p++)
        #pragma unroll
        for (int nt = 0; nt < 8; nt++)
            #pragma unroll
            for (int j = 0; j < 4; j++) acc[p][nt][j] = 0.f;

    const int arow = t >> 3;
    const int ag   = t & 7;

    auto load_chunk = [&](int c, uint32_t buf) {
        #pragma unroll
        for (int it = 0; it < 4; it++) {
            int row = arow + it * 32;
            int gm = m0 + row;
            unsigned ok = (gm < N_NODES) ? 16u : 0u;
            int gmc = (gm < N_NODES) ? gm : 0;
            cp16z(buf + row * AST + ag * 16,
                  g_a16 + (size_t)gmc * 128 + c * 32 + ag * 4, ok);
        }
        #pragma unroll
        for (int it = 0; it < 6; it++) {
            int idx = t + it * 256;
            int p = idx >> 9;
            int rem = idx & 511;
            int row = rem >> 3;
            int g = rem & 7;
            cp16z(buf + SB_OFF + p * SBUF + row * AST + g * 16,
                  g_whi + row * 768 + p * 256 + c * 64 + g * 8, 16u);
        }
        CP_COMMIT();
    };

    load_chunk(0, sb);

    for (int c = 0; c < 4; c++) {
        if (c < 3) {
            load_chunk(c + 1, sb + ((c + 1) & 1) * BUFSZ);
            CP_WAIT(1);
        } else {
            CP_WAIT(0);
        }
        __syncthreads();

        uint32_t buf = sb + (c & 1) * BUFSZ;

        #pragma unroll
        for (int ks = 0; ks < 4; ks++) {
            int ar = w * 16 + (lane & 15);
            uint32_t aoff = (uint32_t)(ar * AST + ks * 32 + ((lane >> 4) << 4));
            uint32_t a0, a1, a2, a3;
            ldsm4(a0, a1, a2, a3, buf + aoff);

            #pragma unroll
            for (int np = 0; np < 4; np++) {
                int nrow = np * 16 + (lane & 7) + ((lane & 16) ? 8 : 0);
                uint32_t boff = (uint32_t)(nrow * AST + ks * 32 + ((lane & 8) ? 16 : 0));
                #pragma unroll
                for (int p = 0; p < 3; p++) {
                    uint32_t b0, b1, b2, b3;
                    ldsm4(b0, b1, b2, b3, buf + SB_OFF + p * SBUF + boff);
                    mma_f16(acc[p][np * 2],     a0, a1, a2, a3, b0, b1);
                    mma_f16(acc[p][np * 2 + 1], a0, a1, a2, a3, b2, b3);
                }
            }
        }
        __syncthreads();
    }

    // ---- epilogue: x = D0 + c1*D1 + c2*D2 + bias; fused BN column stats ----
    float* swsum = (float*)smem;
    float* swsq  = (float*)(smem + 2048);

    int rowA = m0 + w * 16 + (lane >> 2);
    int rowB = rowA + 8;
    bool va = rowA < N_NODES, vb = rowB < N_NODES;
    float c1a = 0.f, c2a = 0.f, c1b = 0.f, c2b = 0.f;
    if (va) { c1a = g_c1[rowA]; c2a = g_c2[rowA]; }
    if (vb) { c1b = g_c1[rowB]; c2b = g_c2[rowB]; }

    #pragma unroll
    for (int nt = 0; nt < 8; nt++) {
        int col = nt * 8 + (lane & 3) * 2;
        float b0 = bias[col];
        float b1 = bias[col + 1];
        float x0a = acc[0][nt][0] + c1a * acc[1][nt][0] + c2a * acc[2][nt][0] + b0;
        float x1a = acc[0][nt][1] + c1a * acc[1][nt][1] + c2a * acc[2][nt][1] + b1;
        float x0b = acc[0][nt][2] + c1b * acc[1][nt][2] + c2b * acc[2][nt][2] + b0;
        float x1b = acc[0][nt][3] + c1b * acc[1][nt][3] + c2b * acc[2][nt][3] + b1;
        if (va) *(float2*)(g_x + (size_t)rowA * 64 + col) = make_float2(x0a, x1a);
        if (vb) *(float2*)(g_x + (size_t)rowB * 64 + col) = make_float2(x0b, x1b);

        float s0 = (va ? x0a : 0.f) + (vb ? x0b : 0.f);
        float s1 = (va ? x1a : 0.f) + (vb ? x1b : 0.f);
        float q0 = (va ? x0a * x0a : 0.f) + (vb ? x0b * x0b : 0.f);
        float q1 = (va ? x1a * x1a : 0.f) + (vb ? x1b * x1b : 0.f);
        #pragma unroll
        for (int o = 4; o <= 16; o <<= 1) {
            s0 += __shfl_xor_sync(0xffffffffu, s0, o);
            s1 += __shfl_xor_sync(0xffffffffu, s1, o);
            q0 += __shfl_xor_sync(0xffffffffu, q0, o);
            q1 += __shfl_xor_sync(0xffffffffu, q1, o);
        }
        if (lane < 4) {
            swsum[w * 64 + nt * 8 + lane * 2]     = s0;
            swsum[w * 64 + nt * 8 + lane * 2 + 1] = s1;
            swsq [w * 64 + nt * 8 + lane * 2]     = q0;
            swsq [w * 64 + nt * 8 + lane * 2 + 1] = q1;
        }
    }
    __syncthreads();
    if (t < 64) {
        float s = 0.f, q = 0.f;
        #pragma unroll
        for (int k = 0; k < 8; k++) {
            s += swsum[k * 64 + t];
            q += swsq[k * 64 + t];
        }
        atomicAdd(&g_colsum[t], s);
        atomicAdd(&g_colsq[t], q);
    }
}

// ---------------- K6: BN + ReLU + residual (2x float4 per thread) ------------------
__global__ void k_final(const float* __restrict__ h,
                        const float* __restrict__ gamma,
                        const float* __restrict__ beta,
                        float* __restrict__ out) {
    const int HALF = N_NODES * F_DIM / 8;   // 400000 float4s per half (mult of 16)
    int i = blockIdx.x * blockDim.x + threadIdx.x;
    if (i >= HALF) return;
    int j = (i & 15) * 4;                   // same for i and i+HALF
    const float invN = 1.0f / (float)N_NODES;
    float4 cs = *(const float4*)(g_colsum + j);
    float4 cq = *(const float4*)(g_colsq + j);
    float4 gm = *(const float4*)(gamma + j);
    float4 bt = *(const float4*)(beta + j);

    float4 xv0 = ((const float4*)g_x)[i];
    float4 hv0 = ((const float4*)h)[i];
    float4 xv1 = ((const float4*)g_x)[i + HALF];
    float4 hv1 = ((const float4*)h)[i + HALF];

    float mu_x = cs.x * invN, iv_x = rsqrtf(cq.x * invN - mu_x * mu_x + EPS_BN);
    float mu_y = cs.y * invN, iv_y = rsqrtf(cq.y * invN - mu_y * mu_y + EPS_BN);
    float mu_z = cs.z * invN, iv_z = rsqrtf(cq.z * invN - mu_z * mu_z + EPS_BN);
    float mu_w = cs.w * invN, iv_w = rsqrtf(cq.w * invN - mu_w * mu_w + EPS_BN);

    float4 r0, r1;
    r0.x = hv0.x + fmaxf(gm.x * (xv0.x - mu_x) * iv_x + bt.x, 0.f);
    r0.y = hv0.y + fmaxf(gm.y * (xv0.y - mu_y) * iv_y + bt.y, 0.f);
    r0.z = hv0.z + fmaxf(gm.z * (xv0.z - mu_z) * iv_z + bt.z, 0.f);
    r0.w = hv0.w + fmaxf(gm.w * (xv0.w - mu_w) * iv_w + bt.w, 0.f);
    r1.x = hv1.x + fmaxf(gm.x * (xv1.x - mu_x) * iv_x + bt.x, 0.f);
    r1.y = hv1.y + fmaxf(gm.y * (xv1.y - mu_y) * iv_y + bt.y, 0.f);
    r1.z = hv1.z + fmaxf(gm.z * (xv1.z - mu_z) * iv_z + bt.z, 0.f);
    r1.w = hv1.w + fmaxf(gm.w * (xv1.w - mu_w) * iv_w + bt.w, 0.f);

    ((float4*)out)[i] = r0;
    ((float4*)out)[i + HALF] = r1;
}

// ---------------- launch ------------------------------------------------------------
extern "C" void kernel_launch(void* const* d_in, const int* in_sizes, int n_in,
                              void* d_out, int out_size) {
    const float* h     = (const float*)d_in[0];
    const int*   src   = (const int*)d_in[1];
    const int*   dst   = (const int*)d_in[2];
    const float* W     = (const float*)d_in[3];
    const float* b     = (const float*)d_in[4];
    const float* gamma = (const float*)d_in[5];
    const float* beta  = (const float*)d_in[6];
    float* out = (float*)d_out;

    cudaFuncSetAttribute(k_gemm_mma, cudaFuncAttributeMaxDynamicSharedMemorySize, SMEM_MM);

    k_hist_wprep<<<(N_EDGES / 4 + 255) / 256, 256>>>(dst, W);
    k_scan<<<NB, 256>>>();
    k_scatter<<<(N_EDGES / 4 + 255) / 256, 256>>>(src, dst);
    k_agg<<<(N_NODES + 7) / 8, 256>>>(h);
    k_gemm_mma<<<(N_NODES + 127) / 128, 256, SMEM_MM>>>(b);
    k_final<<<(N_NODES * F_DIM / 8 + 255) / 256, 256>>>(h, gamma, beta, out);
}